// round 7
// baseline (speedup 1.0000x reference)
#include <cuda_runtime.h>
#include <cuda_fp16.h>
#include <cstdint>

#define N_NODES   100000
#define N_EDGES   1600000
#define VOCAB     128
#define D         30
#define DPAD      32
#define N_CLASSES 5
#define SCAN_NB   98         // 98 * 1024 = 100352 >= N_NODES
#define FLAGBIT   0x40000000
#define NPB       64         // nodes per block in layer kernels

// Scratch (device globals; float4 arrays => 16B alignment for LDG.128)
__device__ float4 g_hsA[N_NODES * 4];           // fp16 features: 64B/node = 4 float4
__device__ float4 g_hsB[N_NODES * 4];
__device__ float  g_inv[N_NODES];
__device__ int    g_pre[2 * N_NODES + 128];     // cnt | degr | scan state (memset once)
__device__ int    g_off[N_NODES + 1];
__device__ int    g_cur[N_NODES];
__device__ int    g_srow[N_EDGES];

// ---------------------------------------------------------------------------
__device__ __forceinline__ __half2 H2(float f) { return *(const __half2*)&f; }
__device__ __forceinline__ float   F(__half2 h) { return *(const float*)&h; }

// componentwise fp16x2 add of two 16B rows
__device__ __forceinline__ float4 hadd4(float4 a, float4 b) {
    float4 r;
    r.x = F(__hadd2(H2(a.x), H2(b.x)));
    r.y = F(__hadd2(H2(a.y), H2(b.y)));
    r.z = F(__hadd2(H2(a.z), H2(b.z)));
    r.w = F(__hadd2(H2(a.w), H2(b.w)));
    return r;
}

// ---------------------------------------------------------------------------
__global__ void k_hist(const int* __restrict__ row, const int* __restrict__ col,
                       int* __restrict__ cnt, int* __restrict__ degr) {
    int e = blockIdx.x * blockDim.x + threadIdx.x;
    if (e < N_EDGES) {
        atomicAdd(&cnt[col[e]], 1);
        atomicAdd(&degr[row[e]], 1);
    }
}

// Single-pass scan (98 blocks x 256 thr x 4 items): off/cur + inv_deg + hs0.
__global__ void __launch_bounds__(256)
k_scan(const int* __restrict__ cnt, const int* __restrict__ degr,
       const int* __restrict__ x, const float* __restrict__ emb,
       int* __restrict__ off, int* __restrict__ cur,
       float* __restrict__ inv, __half2* __restrict__ hs0,
       int* __restrict__ state) {
    __shared__ int wsum[8];
    __shared__ int sPrefix;
    int t = threadIdx.x, bid = blockIdx.x;
    int lane = t & 31, wid = t >> 5;
    int base = bid * 1024 + t * 4;

    int v[4];
    #pragma unroll
    for (int j = 0; j < 4; j++) {
        int i = base + j;
        v[j] = (i < N_NODES) ? cnt[i] : 0;
    }
    int tsum = v[0] + v[1] + v[2] + v[3];

    int inc = tsum;
    #pragma unroll
    for (int d = 1; d < 32; d <<= 1) {
        int u = __shfl_up_sync(~0u, inc, d);
        if (lane >= d) inc += u;
    }
    if (lane == 31) wsum[wid] = inc;
    __syncthreads();
    if (wid == 0) {
        int w = (lane < 8) ? wsum[lane] : 0;
        #pragma unroll
        for (int d = 1; d < 8; d <<= 1) {
            int u = __shfl_up_sync(~0u, w, d);
            if (lane >= d) w += u;
        }
        if (lane < 8) wsum[lane] = w;
    }
    __syncthreads();
    int warpBase = (wid == 0) ? 0 : wsum[wid - 1];
    int texcl = warpBase + inc - tsum;
    int blockAgg = wsum[7];
    __syncthreads();

    if (t == 0) atomicExch(&state[bid], blockAgg | FLAGBIT);

    int pref = 0;
    if (t < bid) {
        int s;
        do { s = atomicOr(&state[t], 0); } while (!(s & FLAGBIT));
        pref = s & ~FLAGBIT;
    }
    #pragma unroll
    for (int d = 16; d > 0; d >>= 1) pref += __shfl_down_sync(~0u, pref, d);
    if (lane == 0) wsum[wid] = pref;
    __syncthreads();
    if (t == 0) {
        int p = 0;
        #pragma unroll
        for (int j = 0; j < 8; j++) p += wsum[j];
        sPrefix = p;
    }
    __syncthreads();

    int e = sPrefix + texcl;
    #pragma unroll
    for (int j = 0; j < 4; j++) {
        int i = base + j;
        if (i < N_NODES) {
            off[i] = e;
            cur[i] = e;
            float iv = 1.0f / (1.0f + (float)degr[i]);   // +1 = self loop
            inv[i] = iv;
            const float* er = emb + x[i] * D;
            __half2* hrow = hs0 + i * 16;
            #pragma unroll
            for (int d = 0; d < 15; d++)
                hrow[d] = __floats2half2_rn(er[2 * d] * iv, er[2 * d + 1] * iv);
            hrow[15] = __floats2half2_rn(0.0f, 0.0f);
            if (i == N_NODES - 1) off[N_NODES] = e + v[j];
        }
        e += v[j];
    }
}

__global__ void k_scatter(const int* __restrict__ row, const int* __restrict__ col,
                          int* __restrict__ cur, int* __restrict__ srow) {
    int e = blockIdx.x * blockDim.x + threadIdx.x;
    if (e < N_EDGES) {
        int p = atomicAdd(&cur[col[e]], 1);
        srow[p] = row[e];
    }
}

// ---------------------------------------------------------------------------
// Fused layer. Phase 1: 4 lanes/node, LDG.128 per edge row; 8-edge unroll with
// depth-3 fp16 HADD2 tree, fp32 accumulate once per group. Phase 2: matmul
// epilogue; FINAL emits 5-class logits.
template <bool FINAL>
__global__ void __launch_bounds__(256)
k_layer(const int* __restrict__ off, const int* __restrict__ srow,
        const float4* __restrict__ hs,
        const float* __restrict__ W, const float* __restrict__ b,
        const float* __restrict__ inv,
        __half2* __restrict__ hs_out,
        const float* __restrict__ Wout, const float* __restrict__ bout,
        float* __restrict__ out) {
    __shared__ float  sAgg[NPB][33];
    __shared__ float2 Wt2[D * 16];     // Wt2[k*16+l] = (W[2l][k], W[2l+1][k])
    __shared__ float2 b2s[16];
    __shared__ float  Wo[N_CLASSES * D];
    __shared__ float  bo[N_CLASSES];

    int tid = threadIdx.x;
    for (int i = tid; i < D * 16; i += 256) {
        int l = i & 15, k = i >> 4;
        float w0 = (2 * l     < D) ? W[(2 * l)     * D + k] : 0.0f;
        float w1 = (2 * l + 1 < D) ? W[(2 * l + 1) * D + k] : 0.0f;
        Wt2[i] = make_float2(w0, w1);
    }
    if (tid < 16) {
        int l = tid;
        b2s[l] = make_float2((2 * l < D) ? b[2 * l] : 0.0f,
                             (2 * l + 1 < D) ? b[2 * l + 1] : 0.0f);
    }
    if (FINAL) {
        if (tid < N_CLASSES * D) Wo[tid] = Wout[tid];
        if (tid < N_CLASSES)     bo[tid] = bout[tid];
    }

    // ---- Phase 1: aggregation (4 lanes per node, 8-edge fp16 tree) ----
    {
        int g = tid >> 2, lane = tid & 3;
        int n = blockIdx.x * NPB + g;
        if (n >= N_NODES) n = N_NODES - 1;       // clamp: benign duplicates

        int beg = off[n], end = off[n + 1];
        float4 sv = __ldg(hs + (n << 2) + lane); // self loop
        float2 a0 = __half22float2(H2(sv.x));
        float2 a1 = __half22float2(H2(sv.y));
        float2 a2 = __half22float2(H2(sv.z));
        float2 a3 = __half22float2(H2(sv.w));

        int i = beg;
        for (; i + 7 < end; i += 8) {
            int s0 = __ldg(srow + i);     int s1 = __ldg(srow + i + 1);
            int s2 = __ldg(srow + i + 2); int s3 = __ldg(srow + i + 3);
            int s4 = __ldg(srow + i + 4); int s5 = __ldg(srow + i + 5);
            int s6 = __ldg(srow + i + 6); int s7 = __ldg(srow + i + 7);
            float4 v0 = __ldg(hs + (s0 << 2) + lane);
            float4 v1 = __ldg(hs + (s1 << 2) + lane);
            float4 v2 = __ldg(hs + (s2 << 2) + lane);
            float4 v3 = __ldg(hs + (s3 << 2) + lane);
            float4 v4 = __ldg(hs + (s4 << 2) + lane);
            float4 v5 = __ldg(hs + (s5 << 2) + lane);
            float4 v6 = __ldg(hs + (s6 << 2) + lane);
            float4 v7 = __ldg(hs + (s7 << 2) + lane);
            float4 p01 = hadd4(v0, v1);
            float4 p23 = hadd4(v2, v3);
            float4 p45 = hadd4(v4, v5);
            float4 p67 = hadd4(v6, v7);
            float4 q03 = hadd4(p01, p23);
            float4 q47 = hadd4(p45, p67);
            float4 r   = hadd4(q03, q47);
            float2 u;
            u = __half22float2(H2(r.x)); a0.x += u.x; a0.y += u.y;
            u = __half22float2(H2(r.y)); a1.x += u.x; a1.y += u.y;
            u = __half22float2(H2(r.z)); a2.x += u.x; a2.y += u.y;
            u = __half22float2(H2(r.w)); a3.x += u.x; a3.y += u.y;
        }
        for (; i < end; i++) {
            int s0 = __ldg(srow + i);
            float4 v0 = __ldg(hs + (s0 << 2) + lane);
            float2 u;
            u = __half22float2(H2(v0.x)); a0.x += u.x; a0.y += u.y;
            u = __half22float2(H2(v0.y)); a1.x += u.x; a1.y += u.y;
            u = __half22float2(H2(v0.z)); a2.x += u.x; a2.y += u.y;
            u = __half22float2(H2(v0.w)); a3.x += u.x; a3.y += u.y;
        }
        float* row = &sAgg[g][lane * 8];
        row[0] = a0.x; row[1] = a0.y; row[2] = a1.x; row[3] = a1.y;
        row[4] = a2.x; row[5] = a2.y; row[6] = a3.x; row[7] = a3.y;
    }
    __syncthreads();

    // ---- Phase 2: matmul + relu (+ final projection), 16 lanes/node, 4 passes ----
    int l = tid & 15, g2 = tid >> 4;
    #pragma unroll
    for (int p = 0; p < 4; p++) {
        int gl = p * 16 + g2;
        int n = blockIdx.x * NPB + gl;
        if (n >= N_NODES) n = N_NODES - 1;     // clamp: benign duplicates

        float2 o = b2s[l];
        #pragma unroll
        for (int k = 0; k < D; k++) {
            float av = sAgg[gl][k];
            float2 w = Wt2[(k << 4) + l];
            o.x = fmaf(av, w.x, o.x);
            o.y = fmaf(av, w.y, o.y);
        }
        o.x = fmaxf(o.x, 0.0f);
        o.y = fmaxf(o.y, 0.0f);
        if (2 * l >= D)     o.x = 0.0f;
        if (2 * l + 1 >= D) o.y = 0.0f;

        if (!FINAL) {
            float iv = inv[n];
            hs_out[(n << 4) + l] = __floats2half2_rn(o.x * iv, o.y * iv);
        } else {
            __syncwarp();
            sAgg[gl][2 * l]     = o.x;
            sAgg[gl][2 * l + 1] = o.y;
            __syncwarp();
            if (l < N_CLASSES) {
                float acc = bo[l];
                #pragma unroll
                for (int k = 0; k < D; k++)
                    acc = fmaf(sAgg[gl][k], Wo[l * D + k], acc);
                out[n * N_CLASSES + l] = acc;
            }
            __syncwarp();
        }
    }
}

// ---------------------------------------------------------------------------
extern "C" void kernel_launch(void* const* d_in, const int* in_sizes, int n_in,
                              void* d_out, int out_size) {
    const int*   x    = (const int*)  d_in[0];
    const int*   ei   = (const int*)  d_in[1];   // [2, E] row-major
    const float* emb  = (const float*)d_in[2];
    const float* W1   = (const float*)d_in[3];
    const float* b1   = (const float*)d_in[4];
    const float* W2   = (const float*)d_in[5];
    const float* b2   = (const float*)d_in[6];
    const float* W3   = (const float*)d_in[7];
    const float* b3   = (const float*)d_in[8];
    const float* Wout = (const float*)d_in[9];
    const float* bout = (const float*)d_in[10];
    float* out = (float*)d_out;

    const int* row = ei;
    const int* col = ei + N_EDGES;

    float4 *hsA, *hsB;
    float *inv;
    int *pre, *off, *cur, *srow;
    cudaGetSymbolAddress((void**)&hsA,  g_hsA);
    cudaGetSymbolAddress((void**)&hsB,  g_hsB);
    cudaGetSymbolAddress((void**)&inv,  g_inv);
    cudaGetSymbolAddress((void**)&pre,  g_pre);
    cudaGetSymbolAddress((void**)&off,  g_off);
    cudaGetSymbolAddress((void**)&cur,  g_cur);
    cudaGetSymbolAddress((void**)&srow, g_srow);

    int* cnt   = pre;
    int* degr  = pre + N_NODES;
    int* state = pre + 2 * N_NODES;

    const int NT = 256;
    const int gEdge  = N_EDGES / NT;              // 6250 exact
    const int gLayer = (N_NODES + NPB - 1) / NPB; // 1563

    cudaMemsetAsync(pre, 0, (2 * N_NODES + 128) * sizeof(int));
    k_hist<<<gEdge, NT>>>(row, col, cnt, degr);
    k_scan<<<SCAN_NB, NT>>>(cnt, degr, x, emb, off, cur, inv,
                            (__half2*)hsA, state);
    k_scatter<<<gEdge, NT>>>(row, col, cur, srow);

    k_layer<false><<<gLayer, NT>>>(off, srow, hsA, W1, b1, inv, (__half2*)hsB,
                                   nullptr, nullptr, nullptr);
    k_layer<false><<<gLayer, NT>>>(off, srow, hsB, W2, b2, inv, (__half2*)hsA,
                                   nullptr, nullptr, nullptr);
    k_layer<true> <<<gLayer, NT>>>(off, srow, hsA, W3, b3, inv, nullptr,
                                   Wout, bout, out);
}